// round 7
// baseline (speedup 1.0000x reference)
#include <cuda_runtime.h>
#include <cuda_bf16.h>

// ---------------------------------------------------------------------------
// Fused SSIM loss, separable 11-tap Gaussian, f32x2-packed (FFMA2) math.
//   result = 1 - (mean(ssim(f,s1)) + mean(ssim(f,s2))) / 2
// 8 blur channels paired into 4 f32x2 lanes:
//   P0=(f,a)  P1=(f^2,a^2)  P2=(b,b^2)  P3=(f*a,f*b)
// 16-row tiles + 84-reg cap -> 3 blocks/SM (24 warps) for latency hiding.
// ---------------------------------------------------------------------------

#define IMG_W 512
#define IMG_H 512
#define N_PLANES 48               // B*C = 16*3
#define OUT_TW 54
#define OUT_TH 16
#define VB_STRIDE 66              // row stride in float2 (ull) units
#define SMEM_ULL (4 * OUT_TH * VB_STRIDE)
#define SMEM_BYTES (SMEM_ULL * 8) // 33792
#define GRID_X 10
#define GRID_Y 32
#define N_BLOCKS (GRID_X * GRID_Y * N_PLANES)   // 15360

typedef unsigned long long ull;

__device__ __forceinline__ ull pk2(float lo, float hi) {
    ull r; asm("mov.b64 %0, {%1, %2};" : "=l"(r) : "f"(lo), "f"(hi)); return r;
}
__device__ __forceinline__ void upk2(float& lo, float& hi, ull v) {
    asm("mov.b64 {%0, %1}, %2;" : "=f"(lo), "=f"(hi) : "l"(v));
}
__device__ __forceinline__ ull fma2(ull a, ull b, ull c) {
    ull d; asm("fma.rn.f32x2 %0, %1, %2, %3;" : "=l"(d) : "l"(a), "l"(b), "l"(c));
    return d;
}
__device__ __forceinline__ ull mul2(ull a, ull b) {
    ull d; asm("mul.rn.f32x2 %0, %1, %2;" : "=l"(d) : "l"(a), "l"(b));
    return d;
}

__device__ double       g_ssim_acc = 0.0;
__device__ unsigned int g_blk_cnt  = 0;

// tap t (0..10) -> distinct-weight index (symmetry)
#define TAPIDX(t) ((t) < 6 ? (t) : 10 - (t))

extern "C" __global__ void __launch_bounds__(256, 3)
ssim_fused_kernel(const float* __restrict__ F,
                  const float* __restrict__ S1,
                  const float* __restrict__ S2,
                  float* __restrict__ out) {
    extern __shared__ ull vb[];   // [4 pair][16 rows][VB_STRIDE]

    const int tid = threadIdx.x;
    const int x0 = blockIdx.x * OUT_TW;
    const int y0 = blockIdx.y * OUT_TH;
    const int plane = blockIdx.z;
    const float* __restrict__ Fp  = F  + (size_t)plane * (IMG_H * IMG_W);
    const float* __restrict__ S1p = S1 + (size_t)plane * (IMG_H * IMG_W);
    const float* __restrict__ S2p = S2 + (size_t)plane * (IMG_H * IMG_W);

    // 6 distinct Gaussian taps (sigma=1.5, normalized), packed {w,w}.
    constexpr float G6[6] = {
        0.00102838f, 0.00759874f, 0.03600077f,
        0.10936055f, 0.21300554f, 0.26601173f
    };
    ull W6[6];
    #pragma unroll
    for (int t = 0; t < 6; ++t) {
        unsigned u = __float_as_uint(G6[t]);
        W6[t] = ((ull)u << 32) | u;
    }

    // ---------------- Phase A: vertical blur, packed accumulators -----------
    {
        const int col   = tid & 63;        // 0..63 input column
        const int chunk = tid >> 6;        // 0..3 -> v-rows [chunk*4, +4)
        const int xg = x0 - 5 + col;
        const bool colok = ((unsigned)xg < (unsigned)IMG_W);
        const int rbase = y0 + chunk * 4 - 5;

        ull acc[4][4];
        #pragma unroll
        for (int j = 0; j < 4; ++j)
            #pragma unroll
            for (int p = 0; p < 4; ++p) acc[j][p] = 0ull;

        #pragma unroll
        for (int r = 0; r < 14; ++r) {
            const int ry = rbase + r;
            float f = 0.0f, a = 0.0f, b = 0.0f;
            if (colok && (unsigned)ry < (unsigned)IMG_H) {
                const int idx = ry * IMG_W + xg;
                f = Fp[idx]; a = S1p[idx]; b = S2p[idx];
            }
            const ull P0 = pk2(f, a);
            const ull P1 = mul2(P0, P0);          // (f^2, a^2)
            const ull P2 = pk2(b, b * b);         // (b, b^2)
            const ull P3 = pk2(f * a, f * b);     // (fa, fb)
            const int jlo = (r - 10) > 0 ? (r - 10) : 0;
            const int jhi = r < 3 ? r : 3;
            #pragma unroll
            for (int j = jlo; j <= jhi; ++j) {
                const ull w = W6[TAPIDX(r - j)];
                acc[j][0] = fma2(P0, w, acc[j][0]);
                acc[j][1] = fma2(P1, w, acc[j][1]);
                acc[j][2] = fma2(P2, w, acc[j][2]);
                acc[j][3] = fma2(P3, w, acc[j][3]);
            }
        }

        #pragma unroll
        for (int j = 0; j < 4; ++j) {
            const int vr = chunk * 4 + j;
            #pragma unroll
            for (int p = 0; p < 4; ++p)
                vb[(p * OUT_TH + vr) * VB_STRIDE + col] = acc[j][p];
        }
    }
    __syncthreads();

    // ---------------- Phase B: horizontal blur (rolling) + epilogue ---------
    float lsum = 0.0f;
    {
        const int row  = tid >> 4;         // 0..15
        const int slot = tid & 15;         // 0..15 -> 4 outputs each
        const int c0 = slot * 4;           // out-col base

        if (c0 < OUT_TW) {                 // slots 14,15 idle (c0 >= 54)
            ull hb[4][4];
            #pragma unroll
            for (int p = 0; p < 4; ++p) {
                const ull* __restrict__ src =
                    vb + (p * OUT_TH + row) * VB_STRIDE + c0;
                #pragma unroll
                for (int j = 0; j < 4; ++j) hb[p][j] = 0ull;
                #pragma unroll
                for (int k = 0; k < 14; ++k) {     // max idx c0+13 <= 65
                    const ull w = src[k];
                    const int jlo = (k - 10) > 0 ? (k - 10) : 0;
                    const int jhi = k < 3 ? k : 3;
                    #pragma unroll
                    for (int j = jlo; j <= jhi; ++j)
                        hb[p][j] = fma2(w, W6[TAPIDX(k - j)], hb[p][j]);
                }
            }

            const float C1c = 1e-4f;   // 0.01^2
            const float C2c = 9e-4f;   // 0.03^2
            #pragma unroll
            for (int j = 0; j < 4; ++j) {
                const int lc = c0 + j;
                if (lc < OUT_TW && (x0 + lc) < IMG_W) {
                    float mu1, mu2, Bff, Baa, mu3, Bbb, Bfa, Bfb;
                    upk2(mu1, mu2, hb[0][j]);
                    upk2(Bff, Baa, hb[1][j]);
                    upk2(mu3, Bbb, hb[2][j]);
                    upk2(Bfa, Bfb, hb[3][j]);
                    const float m11 = mu1 * mu1, m22 = mu2 * mu2;
                    const float m33 = mu3 * mu3;
                    const float m12 = mu1 * mu2, m13 = mu1 * mu3;
                    const float s11 = Bff - m11;
                    const float s22 = Baa - m22;
                    const float s33 = Bbb - m33;
                    const float s12 = Bfa - m12;
                    const float s13 = Bfb - m13;
                    const float n1 = (2.0f * m12 + C1c) * (2.0f * s12 + C2c);
                    const float d1 = (m11 + m22 + C1c) * (s11 + s22 + C2c);
                    const float n2 = (2.0f * m13 + C1c) * (2.0f * s13 + C2c);
                    const float d2 = (m11 + m33 + C1c) * (s11 + s33 + C2c);
                    lsum += __fdividef(n1, d1) + __fdividef(n2, d2);
                }
            }
        }
    }

    // ---------------- reduction + self-finalizing last block ----------------
    #pragma unroll
    for (int o = 16; o; o >>= 1)
        lsum += __shfl_down_sync(0xffffffffu, lsum, o);
    __shared__ float wsum[8];
    if ((tid & 31) == 0) wsum[tid >> 5] = lsum;
    __syncthreads();
    if (tid < 8) {
        float v = wsum[tid];
        #pragma unroll
        for (int o = 4; o; o >>= 1)
            v += __shfl_down_sync(0x000000ffu, v, o);
        if (tid == 0) {
            atomicAdd(&g_ssim_acc, (double)v);
            __threadfence();
            const unsigned old = atomicAdd(&g_blk_cnt, 1u);
            if (old == (unsigned)(N_BLOCKS - 1)) {
                __threadfence();
                volatile double* va = &g_ssim_acc;
                const double total = *va;
                const double npix = (double)N_PLANES * IMG_H * IMG_W;
                out[0] = (float)(1.0 - total / (2.0 * npix));
                *va = 0.0;                       // reset for next replay
                *(volatile unsigned*)&g_blk_cnt = 0u;
                __threadfence();
            }
        }
    }
}

extern "C" void kernel_launch(void* const* d_in, const int* in_sizes, int n_in,
                              void* d_out, int out_size) {
    (void)in_sizes; (void)n_in; (void)out_size;
    const float* F  = (const float*)d_in[0];
    const float* S1 = (const float*)d_in[1];
    const float* S2 = (const float*)d_in[2];
    float* out = (float*)d_out;

    dim3 grid(GRID_X, GRID_Y, N_PLANES);   // 10 x 32 x 48 = 15360 blocks
    ssim_fused_kernel<<<grid, 256, SMEM_BYTES>>>(F, S1, S2, out);
}

// round 8
// speedup vs baseline: 1.4285x; 1.4285x over previous
#include <cuda_runtime.h>
#include <cuda_bf16.h>

// ---------------------------------------------------------------------------
// Fused SSIM loss, separable 11-tap Gaussian, f32x2-packed (FFMA2) math.
//   result = 1 - (mean(ssim(f,s1)) + mean(ssim(f,s2))) / 2
// Channels paired into 4 f32x2 lanes:
//   P0=(f,a)  P1=(f^2,a^2)  P2=(b,b^2)  P3=(f*a,f*b)
// v-buffer stored TRANSPOSED [pair][col][row] so phase-B warp lanes (rows)
// read consecutive ull -> conflict-free LDS.64. Interior blocks skip all
// border predicates.
// ---------------------------------------------------------------------------

#define IMG_W 512
#define IMG_H 512
#define N_PLANES 48               // B*C = 16*3
#define OUT_TW 54
#define OUT_TH 32
#define IN_TW 64
#define COL_STRIDE 33             // ull per column (32 rows + 1 pad)
#define SMEM_ULL (4 * IN_TW * COL_STRIDE + 128)   // +128 overread slack
#define SMEM_BYTES (SMEM_ULL * 8)                 // 68608
#define GRID_X 10
#define GRID_Y 16
#define N_BLOCKS (GRID_X * GRID_Y * N_PLANES)     // 7680

typedef unsigned long long ull;

__device__ __forceinline__ ull pk2(float lo, float hi) {
    ull r; asm("mov.b64 %0, {%1, %2};" : "=l"(r) : "f"(lo), "f"(hi)); return r;
}
__device__ __forceinline__ void upk2(float& lo, float& hi, ull v) {
    asm("mov.b64 {%0, %1}, %2;" : "=f"(lo), "=f"(hi) : "l"(v));
}
__device__ __forceinline__ ull fma2(ull a, ull b, ull c) {
    ull d; asm("fma.rn.f32x2 %0, %1, %2, %3;" : "=l"(d) : "l"(a), "l"(b), "l"(c));
    return d;
}
__device__ __forceinline__ ull mul2(ull a, ull b) {
    ull d; asm("mul.rn.f32x2 %0, %1, %2;" : "=l"(d) : "l"(a), "l"(b));
    return d;
}

__device__ double       g_ssim_acc = 0.0;
__device__ unsigned int g_blk_cnt  = 0;

// tap t (0..10) -> distinct-weight index (symmetry)
#define TAPIDX(t) ((t) < 6 ? (t) : 10 - (t))

extern "C" __global__ void __launch_bounds__(256, 2)
ssim_fused_kernel(const float* __restrict__ F,
                  const float* __restrict__ S1,
                  const float* __restrict__ S2,
                  float* __restrict__ out) {
    extern __shared__ ull vb[];   // [4 pair][64 col][COL_STRIDE rows]

    const int tid = threadIdx.x;
    const int x0 = blockIdx.x * OUT_TW;
    const int y0 = blockIdx.y * OUT_TH;
    const int plane = blockIdx.z;
    const float* __restrict__ Fp  = F  + (size_t)plane * (IMG_H * IMG_W);
    const float* __restrict__ S1p = S1 + (size_t)plane * (IMG_H * IMG_W);
    const float* __restrict__ S2p = S2 + (size_t)plane * (IMG_H * IMG_W);

    // 6 distinct Gaussian taps (sigma=1.5, normalized), packed {w,w}.
    constexpr float G6[6] = {
        0.00102838f, 0.00759874f, 0.03600077f,
        0.10936055f, 0.21300554f, 0.26601173f
    };
    ull W6[6];
    #pragma unroll
    for (int t = 0; t < 6; ++t) {
        unsigned u = __float_as_uint(G6[t]);
        W6[t] = ((ull)u << 32) | u;
    }

    // ---------------- Phase A: vertical blur, packed accumulators -----------
    {
        const int col   = tid & 63;        // 0..63 input column
        const int chunk = tid >> 6;        // 0..3 -> v-rows [chunk*8, +8)
        const int xg = x0 - 5 + col;
        const int rbase = y0 + chunk * 8 - 5;

        ull acc[8][4];
        #pragma unroll
        for (int j = 0; j < 8; ++j)
            #pragma unroll
            for (int p = 0; p < 4; ++p) acc[j][p] = 0ull;

        const bool interior = (blockIdx.x >= 1) & (blockIdx.x <= 8) &
                              (blockIdx.y >= 1) & (blockIdx.y <= 14);

        if (interior) {
            // no border clamps: loads fold to LDG [base + r*2048]
            const float* pf = Fp  + (rbase * IMG_W + xg);
            const float* pa = S1p + (rbase * IMG_W + xg);
            const float* pb = S2p + (rbase * IMG_W + xg);
            #pragma unroll
            for (int r = 0; r < 18; ++r) {
                const float f = pf[r * IMG_W];
                const float a = pa[r * IMG_W];
                const float b = pb[r * IMG_W];
                const ull P0 = pk2(f, a);
                const ull P1 = mul2(P0, P0);
                const ull P2 = pk2(b, b * b);
                const ull P3 = pk2(f * a, f * b);
                const int jlo = (r - 10) > 0 ? (r - 10) : 0;
                const int jhi = r < 7 ? r : 7;
                #pragma unroll
                for (int j = jlo; j <= jhi; ++j) {
                    const ull w = W6[TAPIDX(r - j)];
                    acc[j][0] = fma2(P0, w, acc[j][0]);
                    acc[j][1] = fma2(P1, w, acc[j][1]);
                    acc[j][2] = fma2(P2, w, acc[j][2]);
                    acc[j][3] = fma2(P3, w, acc[j][3]);
                }
            }
        } else {
            const bool colok = ((unsigned)xg < (unsigned)IMG_W);
            #pragma unroll
            for (int r = 0; r < 18; ++r) {
                const int ry = rbase + r;
                float f = 0.0f, a = 0.0f, b = 0.0f;
                if (colok && (unsigned)ry < (unsigned)IMG_H) {
                    const int idx = ry * IMG_W + xg;
                    f = Fp[idx]; a = S1p[idx]; b = S2p[idx];
                }
                const ull P0 = pk2(f, a);
                const ull P1 = mul2(P0, P0);
                const ull P2 = pk2(b, b * b);
                const ull P3 = pk2(f * a, f * b);
                const int jlo = (r - 10) > 0 ? (r - 10) : 0;
                const int jhi = r < 7 ? r : 7;
                #pragma unroll
                for (int j = jlo; j <= jhi; ++j) {
                    const ull w = W6[TAPIDX(r - j)];
                    acc[j][0] = fma2(P0, w, acc[j][0]);
                    acc[j][1] = fma2(P1, w, acc[j][1]);
                    acc[j][2] = fma2(P2, w, acc[j][2]);
                    acc[j][3] = fma2(P3, w, acc[j][3]);
                }
            }
        }

        // transposed store: vb[p][col][row]
        ull* dst = vb + (size_t)col * COL_STRIDE + chunk * 8;
        #pragma unroll
        for (int p = 0; p < 4; ++p)
            #pragma unroll
            for (int j = 0; j < 8; ++j)
                dst[p * (IN_TW * COL_STRIDE) + j] = acc[j][p];
    }
    __syncthreads();

    // ---------------- Phase B: horizontal blur (rolling) + epilogue ---------
    float lsum = 0.0f;
    {
        const int row   = tid & 31;        // 0..31 (warp lanes = rows)
        const int group = tid >> 5;        // 0..7
        const int c0 = group * 7;          // out-col base (0..49)

        ull hb[4][7];
        #pragma unroll
        for (int p = 0; p < 4; ++p) {
            // lane reads vb[p][c0+k][row]: consecutive ull across lanes
            const ull* __restrict__ src =
                vb + (size_t)p * (IN_TW * COL_STRIDE) + (size_t)c0 * COL_STRIDE + row;
            #pragma unroll
            for (int j = 0; j < 7; ++j) hb[p][j] = 0ull;
            #pragma unroll
            for (int k = 0; k < 17; ++k) {
                const ull w = src[k * COL_STRIDE];
                const int jlo = (k - 10) > 0 ? (k - 10) : 0;
                const int jhi = k < 6 ? k : 6;
                #pragma unroll
                for (int j = jlo; j <= jhi; ++j)
                    hb[p][j] = fma2(w, W6[TAPIDX(k - j)], hb[p][j]);
            }
        }

        const int limit = (OUT_TW < IMG_W - x0) ? OUT_TW : (IMG_W - x0);
        const float C1c = 1e-4f;   // 0.01^2
        const float C2c = 9e-4f;   // 0.03^2
        #pragma unroll
        for (int j = 0; j < 7; ++j) {
            if (c0 + j < limit) {
                float mu1, mu2, Bff, Baa, mu3, Bbb, Bfa, Bfb;
                upk2(mu1, mu2, hb[0][j]);
                upk2(Bff, Baa, hb[1][j]);
                upk2(mu3, Bbb, hb[2][j]);
                upk2(Bfa, Bfb, hb[3][j]);
                const float m11 = mu1 * mu1, m22 = mu2 * mu2, m33 = mu3 * mu3;
                const float m12 = mu1 * mu2, m13 = mu1 * mu3;
                const float s11 = Bff - m11;
                const float s22 = Baa - m22;
                const float s33 = Bbb - m33;
                const float s12 = Bfa - m12;
                const float s13 = Bfb - m13;
                const float n1 = (2.0f * m12 + C1c) * (2.0f * s12 + C2c);
                const float d1 = (m11 + m22 + C1c) * (s11 + s22 + C2c);
                const float n2 = (2.0f * m13 + C1c) * (2.0f * s13 + C2c);
                const float d2 = (m11 + m33 + C1c) * (s11 + s33 + C2c);
                lsum += __fdividef(n1, d1) + __fdividef(n2, d2);
            }
        }
    }

    // ---------------- reduction + self-finalizing last block ----------------
    #pragma unroll
    for (int o = 16; o; o >>= 1)
        lsum += __shfl_down_sync(0xffffffffu, lsum, o);
    __shared__ float wsum[8];
    if ((tid & 31) == 0) wsum[tid >> 5] = lsum;
    __syncthreads();
    if (tid < 8) {
        float v = wsum[tid];
        #pragma unroll
        for (int o = 4; o; o >>= 1)
            v += __shfl_down_sync(0x000000ffu, v, o);
        if (tid == 0) {
            atomicAdd(&g_ssim_acc, (double)v);
            __threadfence();
            const unsigned old = atomicAdd(&g_blk_cnt, 1u);
            if (old == (unsigned)(N_BLOCKS - 1)) {
                __threadfence();
                volatile double* va = &g_ssim_acc;
                const double total = *va;
                const double npix = (double)N_PLANES * IMG_H * IMG_W;
                out[0] = (float)(1.0 - total / (2.0 * npix));
                *va = 0.0;                       // reset for next replay
                *(volatile unsigned*)&g_blk_cnt = 0u;
                __threadfence();
            }
        }
    }
}

extern "C" void kernel_launch(void* const* d_in, const int* in_sizes, int n_in,
                              void* d_out, int out_size) {
    (void)in_sizes; (void)n_in; (void)out_size;
    const float* F  = (const float*)d_in[0];
    const float* S1 = (const float*)d_in[1];
    const float* S2 = (const float*)d_in[2];
    float* out = (float*)d_out;

    cudaFuncSetAttribute(ssim_fused_kernel,
                         cudaFuncAttributeMaxDynamicSharedMemorySize,
                         SMEM_BYTES);

    dim3 grid(GRID_X, GRID_Y, N_PLANES);   // 10 x 16 x 48 = 7680 blocks
    ssim_fused_kernel<<<grid, 256, SMEM_BYTES>>>(F, S1, S2, out);
}